// round 16
// baseline (speedup 1.0000x reference)
#include <cuda_runtime.h>
#include <cuda_fp16.h>

#define NQ 4
#define DIM 16
#define NPARAMS 36

typedef unsigned int u32;

// Inverse of the CNOT-ring row permutation (CNOT(0,1),(1,2),(2,3),(3,0)):
// new_row r takes old_row finv(r). Constexpr -> folds to register renames.
__device__ __forceinline__ constexpr int finv(int r) {
    constexpr int F[16] = {0, 13, 3, 14, 6, 11, 5, 8, 12, 1, 15, 2, 10, 7, 9, 4};
    return F[r];
}

// ---------------- helpers ----------------
__device__ __forceinline__ u32 pack_f16x2(float lo, float hi) {
    const __half2 h2 = __floats2half2_rn(lo, hi);
    return *(const u32*)&h2;
}
__device__ __forceinline__ void f16_split(float lo, float hi, u32& h, u32& l) {
    const __half2 h2 = __floats2half2_rn(lo, hi);
    const float2 f = __half22float2(h2);
    const __half2 l2 = __floats2half2_rn(lo - f.x, hi - f.y);
    h = *(const u32*)&h2;
    l = *(const u32*)&l2;
}
__device__ __forceinline__ void mma_f16(float c[4], const u32 a[4], const u32 b[2]) {
    asm volatile(
        "mma.sync.aligned.m16n8k16.row.col.f32.f16.f16.f32 "
        "{%0,%1,%2,%3}, {%4,%5,%6,%7}, {%8,%9}, {%0,%1,%2,%3};"
        : "+f"(c[0]), "+f"(c[1]), "+f"(c[2]), "+f"(c[3])
        : "r"(a[0]), "r"(a[1]), "r"(a[2]), "r"(a[3]), "r"(b[0]), "r"(b[1]));
}
__device__ __forceinline__ void ldsm_x4(u32 r[4], u32 saddr) {
    asm volatile("ldmatrix.sync.aligned.m8n8.x4.shared.b16 {%0,%1,%2,%3}, [%4];"
                 : "=r"(r[0]), "=r"(r[1]), "=r"(r[2]), "=r"(r[3]) : "r"(saddr));
}

// ---------------------------------------------------------------------------
// Single fused kernel. 1024 patches/block, 784 blocks, 5 blocks/SM.
//   Build warp ROTATES per block ((bid>>2)&3) so co-resident blocks' builds
//   land on different SMSPs instead of all serializing on SMSP 0.
//   Layer 1 of the circuit is a Kronecker product (columns of g0⊗g1⊗g2⊗g3),
//   ~112 FMA instead of 512 dense.
// ---------------------------------------------------------------------------
__global__ void __launch_bounds__(256, 5) quanv_kernel(
    const float* __restrict__ x, const float* __restrict__ params,
    float* __restrict__ out, int npatch)
{
    __shared__ __align__(16) unsigned char stage[8 * 64 * 80];  // 40960 B
    __shared__ __align__(16) u32 sBfrag[32][20];                // 2560 B

    const int bw = (blockIdx.x >> 2) & 3;   // build warp (SMSP = bw)

    // U-build scratch aliased into the BUILD warp's staging slice (dead
    // before that warp stages its own front-phase data).
    unsigned char* const scratch = stage + bw * (64 * 80);
    float (*sUr)[DIM + 1]  = (float(*)[DIM + 1])(scratch);
    float (*sUi)[DIM + 1]  = (float(*)[DIM + 1])(scratch + 1088);
    float (*sCoef)[4]      = (float(*)[4])(scratch + 2176);

    const int tid  = threadIdx.x;
    const int lane = tid & 31;
    const int wrp  = tid >> 5;
    const int g    = lane >> 2;
    const int t    = lane & 3;

    unsigned char* const ws = stage + wrp * (64 * 80);
    const u32 wsa  = (u32)__cvta_generic_to_shared(ws);
    const u32 rowa = wsa + (u32)((lane & 15) * 80 + (lane >> 4) * 16);

    const float HPI = 1.5707963267948966f;

    // ================= build warp: register U build =================
    if (wrp == bw) {
        if (lane < 12) {
            const float t1 = 0.5f * __ldg(&params[3 * lane]);
            const float t2 = 0.5f * __ldg(&params[3 * lane + 1]);
            const float t3 = 0.5f * __ldg(&params[3 * lane + 2]);
            float A, B_, C, D, cf, sf;
            __sincosf(t1 + t3, &B_, &A);
            __sincosf(t1 - t3, &D, &C);
            __sincosf(t2, &sf, &cf);
            float4 co;
            co.x = A * cf;   // p
            co.y = B_ * cf;  // q
            co.z = C * sf;   // u
            co.w = D * sf;   // w
            *(float4*)sCoef[lane] = co;
        }
        __syncwarp();

        const int c = lane & 15;
        float ur[DIM], ui[DIM];

        // ---- layer 1 (4 fused gates) via progressive Kronecker ----
        // Fused gate matrix: M00=(p,-u) M01=(-q,w) M10=(q,w) M11=(p,u).
        // Column of kron: product over wires of g_i[row_i][c_i], c0 = MSB.
        {
            float v2r[2], v2i[2];
            {
                const float4 co = *(const float4*)sCoef[0];
                const bool b = (c >> 3) & 1;
                v2r[0] = b ? -co.y : co.x;  v2i[0] = b ? co.w : -co.z;
                v2r[1] = b ?  co.x : co.y;  v2i[1] = b ? co.z :  co.w;
            }
            float v4r[4], v4i[4];
            {
                const float4 co = *(const float4*)sCoef[1];
                const bool b = (c >> 2) & 1;
                const float g0r = b ? -co.y : co.x, g0i = b ? co.w : -co.z;
                const float g1r = b ?  co.x : co.y, g1i = b ? co.z :  co.w;
#pragma unroll
                for (int j = 0; j < 2; j++) {
                    v4r[2*j]   = v2r[j]*g0r - v2i[j]*g0i;
                    v4i[2*j]   = v2r[j]*g0i + v2i[j]*g0r;
                    v4r[2*j+1] = v2r[j]*g1r - v2i[j]*g1i;
                    v4i[2*j+1] = v2r[j]*g1i + v2i[j]*g1r;
                }
            }
            float v8r[8], v8i[8];
            {
                const float4 co = *(const float4*)sCoef[2];
                const bool b = (c >> 1) & 1;
                const float g0r = b ? -co.y : co.x, g0i = b ? co.w : -co.z;
                const float g1r = b ?  co.x : co.y, g1i = b ? co.z :  co.w;
#pragma unroll
                for (int j = 0; j < 4; j++) {
                    v8r[2*j]   = v4r[j]*g0r - v4i[j]*g0i;
                    v8i[2*j]   = v4r[j]*g0i + v4i[j]*g0r;
                    v8r[2*j+1] = v4r[j]*g1r - v4i[j]*g1i;
                    v8i[2*j+1] = v4r[j]*g1i + v4i[j]*g1r;
                }
            }
            {
                const float4 co = *(const float4*)sCoef[3];
                const bool b = c & 1;
                const float g0r = b ? -co.y : co.x, g0i = b ? co.w : -co.z;
                const float g1r = b ?  co.x : co.y, g1i = b ? co.z :  co.w;
#pragma unroll
                for (int j = 0; j < 8; j++) {
                    ur[2*j]   = v8r[j]*g0r - v8i[j]*g0i;
                    ui[2*j]   = v8r[j]*g0i + v8i[j]*g0r;
                    ur[2*j+1] = v8r[j]*g1r - v8i[j]*g1i;
                    ui[2*j+1] = v8r[j]*g1i + v8i[j]*g1r;
                }
            }
        }
        // ring after layer 1
        {
            float tr[DIM], ti[DIM];
#pragma unroll
            for (int r = 0; r < DIM; r++) { tr[r] = ur[finv(r)]; ti[r] = ui[finv(r)]; }
#pragma unroll
            for (int r = 0; r < DIM; r++) { ur[r] = tr[r]; ui[r] = ti[r]; }
        }

        // ---- layers 2,3: dense gates + ring ----
#pragma unroll
        for (int layer = 1; layer < 3; layer++) {
#pragma unroll
            for (int wi = 0; wi < NQ; wi++) {
                const int bit = 8 >> wi;
                const float4 co = *(const float4*)sCoef[layer * 4 + wi];
                const float p = co.x, q = co.y, u = co.z, w = co.w;
#pragma unroll
                for (int r = 0; r < DIM; r++) {
                    if (r & bit) continue;
                    const int r1 = r | bit;
                    const float v0r = ur[r], v0i = ui[r], v1r = ur[r1], v1i = ui[r1];
                    ur[r]  =  p * v0r + u * v0i - q * v1r - w * v1i;
                    ui[r]  = -u * v0r + p * v0i + w * v1r - q * v1i;
                    ur[r1] =  q * v0r - w * v0i + p * v1r - u * v1i;
                    ui[r1] =  w * v0r + q * v0i + u * v1r + p * v1i;
                }
            }
            {
                float tr[DIM], ti[DIM];
#pragma unroll
                for (int r = 0; r < DIM; r++) { tr[r] = ur[finv(r)]; ti[r] = ui[finv(r)]; }
#pragma unroll
                for (int r = 0; r < DIM; r++) { ur[r] = tr[r]; ui[r] = ti[r]; }
            }
        }

        if (lane < 16) {
#pragma unroll
            for (int r = 0; r < DIM; r++) { sUr[r][c] = ur[r]; sUi[r][c] = ui[r]; }
        }
        __syncwarp();

        {
            u32 frag[16];
#pragma unroll
            for (int nt = 0; nt < 2; nt++) {
                const int kk = 8 * nt + g;
                f16_split(sUr[kk][2 * t],     sUr[kk][2 * t + 1], frag[0 + 2 * nt], frag[8  + 2 * nt]);
                f16_split(sUr[kk][2 * t + 8], sUr[kk][2 * t + 9], frag[1 + 2 * nt], frag[9  + 2 * nt]);
                f16_split(sUi[kk][2 * t],     sUi[kk][2 * t + 1], frag[4 + 2 * nt], frag[12 + 2 * nt]);
                f16_split(sUi[kk][2 * t + 8], sUi[kk][2 * t + 9], frag[5 + 2 * nt], frag[13 + 2 * nt]);
            }
            uint4* dst = (uint4*)sBfrag[lane];
#pragma unroll
            for (int v = 0; v < 4; v++)
                dst[v] = make_uint4(frag[4 * v], frag[4 * v + 1], frag[4 * v + 2], frag[4 * v + 3]);
        }
        __syncwarp();   // scratch reads done before this warp overwrites its slice
    }

    // ---- Z-matrix B fragment (fp16 ±1) ----
    u32 Bz[2];
    {
        const u32 s0 = ((2 * t)     >> (3 - (g & 3))) & 1 ? 0xBC00u : 0x3C00u;
        const u32 s1 = ((2 * t + 1) >> (3 - (g & 3))) & 1 ? 0xBC00u : 0x3C00u;
        const u32 s2 = ((2 * t + 8) >> (3 - (g & 3))) & 1 ? 0xBC00u : 0x3C00u;
        const u32 s3 = ((2 * t + 9) >> (3 - (g & 3))) & 1 ? 0xBC00u : 0x3C00u;
        Bz[0] = s0 | (s1 << 16);
        Bz[1] = s2 | (s3 << 16);
        if (g >= 4) { Bz[0] = 0u; Bz[1] = 0u; }
    }

    u32 Bhr[2][2], Bhi[2][2], Blr[2][2], Bli[2][2];

#pragma unroll
    for (int batch = 0; batch < 2; batch++) {
        const int warpbase = blockIdx.x * 1024 + batch * 512 + wrp * 64;

        // ---- front phase: 2 patches/thread -> stage ----
        const float* basep[2];
#pragma unroll
        for (int pp = 0; pp < 2; pp++) {
            const int p  = warpbase + pp * 32 + lane;
            const int pc = (p < npatch) ? p : (npatch - 1);
            const int b  = pc / 196;
            const int q  = pc - b * 196;
            const int r  = q / 14;
            const int cc = q - r * 14;
            basep[pp] = x + b * 784 + r * 56 + cc * 2;
        }
        float2 V01[2], V23[2];
#pragma unroll
        for (int pp = 0; pp < 2; pp++) {
            V01[pp] = *(const float2*)(basep[pp]);
            V23[pp] = *(const float2*)(basep[pp] + 28);
        }

#pragma unroll
        for (int pp = 0; pp < 2; pp++) {
            float a0, b0, a1, b1, a2, b2, a3, b3;
            __sincosf(V01[pp].x * HPI, &b0, &a0);
            __sincosf(V01[pp].y * HPI, &b1, &a1);
            __sincosf(V23[pp].x * HPI, &b2, &a2);
            __sincosf(V23[pp].y * HPI, &b3, &a3);
            const float q01[4] = { a0 * a1, a0 * b1, b0 * a1, b0 * b1 };
            const float q23[4] = { a2 * a3, a2 * b3, b2 * a3, b2 * b3 };

            u32 ph[8], pl[8];
#pragma unroll
            for (int m = 0; m < 8; m++) {
                const float f01 = q01[m >> 1];
                const float lo = f01 * q23[(2 * m) & 3];
                const float hi = f01 * q23[(2 * m + 1) & 3];
                f16_split(lo, hi, ph[m], pl[m]);
            }

            uint4* slot = (uint4*)(ws + (pp * 32 + lane) * 80);
            slot[0] = make_uint4(ph[0], ph[1], ph[2], ph[3]);
            slot[1] = make_uint4(ph[4], ph[5], ph[6], ph[7]);
            slot[2] = make_uint4(pl[0], pl[1], pl[2], pl[3]);
            slot[3] = make_uint4(pl[4], pl[5], pl[6], pl[7]);
        }

        if (batch == 0) {
            __syncthreads();          // sBfrag + all staging visible
            const uint4* bfv = (const uint4*)sBfrag[lane];
            const uint4 vhr = bfv[0], vhi = bfv[1], vlr = bfv[2], vli = bfv[3];
            Bhr[0][0] = vhr.x; Bhr[0][1] = vhr.y; Bhr[1][0] = vhr.z; Bhr[1][1] = vhr.w;
            Bhi[0][0] = vhi.x; Bhi[0][1] = vhi.y; Bhi[1][0] = vhi.z; Bhi[1][1] = vhi.w;
            Blr[0][0] = vlr.x; Blr[0][1] = vlr.y; Blr[1][0] = vlr.z; Blr[1][1] = vlr.w;
            Bli[0][0] = vli.x; Bli[0][1] = vli.y; Bli[1][0] = vli.z; Bli[1][1] = vli.w;
        } else {
            __syncwarp();             // staging is warp-private
        }

        // ---- MMA phase: 4 tiles ----
#pragma unroll
        for (int T = 0; T < 4; T++) {
            u32 Aph[4], Apl[4];
            ldsm_x4(Aph, rowa + T * 16 * 80);
            ldsm_x4(Apl, rowa + T * 16 * 80 + 32);

            float Cr[2][4], Ci[2][4];
#pragma unroll
            for (int nt = 0; nt < 2; nt++)
#pragma unroll
                for (int k = 0; k < 4; k++) { Cr[nt][k] = 0.0f; Ci[nt][k] = 0.0f; }

#pragma unroll
            for (int nt = 0; nt < 2; nt++) {
                mma_f16(Cr[nt], Aph, Bhr[nt]);
                mma_f16(Cr[nt], Apl, Bhr[nt]);
                mma_f16(Cr[nt], Aph, Blr[nt]);
                mma_f16(Ci[nt], Aph, Bhi[nt]);
                mma_f16(Ci[nt], Apl, Bhi[nt]);
                mma_f16(Ci[nt], Aph, Bli[nt]);
            }

            float pr[2][4];
#pragma unroll
            for (int nt = 0; nt < 2; nt++)
#pragma unroll
                for (int k = 0; k < 4; k++)
                    pr[nt][k] = fmaf(Cr[nt][k], Cr[nt][k], Ci[nt][k] * Ci[nt][k]);

            u32 Ap[4];
            Ap[0] = pack_f16x2(pr[0][0], pr[0][1]);
            Ap[1] = pack_f16x2(pr[0][2], pr[0][3]);
            Ap[2] = pack_f16x2(pr[1][0], pr[1][1]);
            Ap[3] = pack_f16x2(pr[1][2], pr[1][3]);

            float E[4] = {0.0f, 0.0f, 0.0f, 0.0f};
            mma_f16(E, Ap, Bz);

            if (t < 2) {
                const int p0s = warpbase + T * 16 + g;
                const int p1s = p0s + 8;
                if (p0s < npatch) *(float2*)(out + 4 * p0s + 2 * t) = make_float2(E[0], E[1]);
                if (p1s < npatch) *(float2*)(out + 4 * p1s + 2 * t) = make_float2(E[2], E[3]);
            }
        }

        if (batch == 0) __syncwarp();  // MMA reads done before batch-1 restage
    }
}

extern "C" void kernel_launch(void* const* d_in, const int* in_sizes, int n_in,
                              void* d_out, int out_size) {
    const float* x      = (const float*)d_in[0];
    const float* params = (const float*)d_in[1];
    float* out = (float*)d_out;

    const int bsz    = in_sizes[0] / 784;
    const int npatch = bsz * 196;

    const int blocks = (npatch + 1023) / 1024;
    quanv_kernel<<<blocks, 256>>>(x, params, out, npatch);
}

// round 17
// speedup vs baseline: 1.1519x; 1.1519x over previous
#include <cuda_runtime.h>
#include <cuda_fp16.h>

#define NQ 4
#define DIM 16
#define NPARAMS 36

typedef unsigned int u32;

// Inverse of the CNOT-ring row permutation (CNOT(0,1),(1,2),(2,3),(3,0)):
// new_row r takes old_row finv(r). Constexpr -> folds to register renames.
__device__ __forceinline__ constexpr int finv(int r) {
    constexpr int F[16] = {0, 13, 3, 14, 6, 11, 5, 8, 12, 1, 15, 2, 10, 7, 9, 4};
    return F[r];
}

// ---------------- helpers ----------------
__device__ __forceinline__ u32 pack_f16x2(float lo, float hi) {
    const __half2 h2 = __floats2half2_rn(lo, hi);
    return *(const u32*)&h2;
}
__device__ __forceinline__ void f16_split(float lo, float hi, u32& h, u32& l) {
    const __half2 h2 = __floats2half2_rn(lo, hi);
    const float2 f = __half22float2(h2);
    const __half2 l2 = __floats2half2_rn(lo - f.x, hi - f.y);
    h = *(const u32*)&h2;
    l = *(const u32*)&l2;
}
__device__ __forceinline__ void mma_f16(float c[4], const u32 a[4], const u32 b[2]) {
    asm volatile(
        "mma.sync.aligned.m16n8k16.row.col.f32.f16.f16.f32 "
        "{%0,%1,%2,%3}, {%4,%5,%6,%7}, {%8,%9}, {%0,%1,%2,%3};"
        : "+f"(c[0]), "+f"(c[1]), "+f"(c[2]), "+f"(c[3])
        : "r"(a[0]), "r"(a[1]), "r"(a[2]), "r"(a[3]), "r"(b[0]), "r"(b[1]));
}
__device__ __forceinline__ void ldsm_x4(u32 r[4], u32 saddr) {
    asm volatile("ldmatrix.sync.aligned.m8n8.x4.shared.b16 {%0,%1,%2,%3}, [%4];"
                 : "=r"(r[0]), "=r"(r[1]), "=r"(r[2]), "=r"(r[3]) : "r"(saddr));
}

#define SLOT 48   // staging slot stride (32B Ph + 16B pad; conflict-free)

// ---------------------------------------------------------------------------
// Single fused kernel. 1024 patches/block, 784 blocks, 5 blocks/SM.
// psi0 staged as SINGLE fp16 (no low-order Pl term): U is still fp16-split
// (Uh+Ul), so y = Uh*Ph + Ul*Ph. Dropped Uh*Pl costs ~2^-12 (psi0 is unit
// norm, U unitary) -> rel_err ~5e-4, under the 1e-3 threshold.
// ---------------------------------------------------------------------------
__global__ void __launch_bounds__(256, 5) quanv_kernel(
    const float* __restrict__ x, const float* __restrict__ params,
    float* __restrict__ out, int npatch)
{
    __shared__ __align__(16) unsigned char stage[8 * 64 * SLOT];  // 24576 B
    __shared__ __align__(16) u32 sBfrag[32][20];                  // 2560 B

    const int bw = (blockIdx.x >> 2) & 3;   // build warp (rotates SMSP)

    // U-build scratch aliased into the BUILD warp's staging slice (3072 B,
    // needs 2368; dead before that warp stages its own front-phase data).
    unsigned char* const scratch = stage + bw * (64 * SLOT);
    float (*sUr)[DIM + 1]  = (float(*)[DIM + 1])(scratch);
    float (*sUi)[DIM + 1]  = (float(*)[DIM + 1])(scratch + 1088);
    float (*sCoef)[4]      = (float(*)[4])(scratch + 2176);

    const int tid  = threadIdx.x;
    const int lane = tid & 31;
    const int wrp  = tid >> 5;
    const int g    = lane >> 2;
    const int t    = lane & 3;

    unsigned char* const ws = stage + wrp * (64 * SLOT);
    const u32 wsa  = (u32)__cvta_generic_to_shared(ws);
    const u32 rowa = wsa + (u32)((lane & 15) * SLOT + (lane >> 4) * 16);

    const float HPI = 1.5707963267948966f;

    // ================= build warp: register U build =================
    if (wrp == bw) {
        if (lane < 12) {
            const float t1 = 0.5f * __ldg(&params[3 * lane]);
            const float t2 = 0.5f * __ldg(&params[3 * lane + 1]);
            const float t3 = 0.5f * __ldg(&params[3 * lane + 2]);
            float A, B_, C, D, cf, sf;
            __sincosf(t1 + t3, &B_, &A);
            __sincosf(t1 - t3, &D, &C);
            __sincosf(t2, &sf, &cf);
            float4 co;
            co.x = A * cf;   // p
            co.y = B_ * cf;  // q
            co.z = C * sf;   // u
            co.w = D * sf;   // w
            *(float4*)sCoef[lane] = co;
        }
        __syncwarp();

        const int c = lane & 15;
        float ur[DIM], ui[DIM];

        // ---- layer 1 via progressive Kronecker ----
        {
            float v2r[2], v2i[2];
            {
                const float4 co = *(const float4*)sCoef[0];
                const bool b = (c >> 3) & 1;
                v2r[0] = b ? -co.y : co.x;  v2i[0] = b ? co.w : -co.z;
                v2r[1] = b ?  co.x : co.y;  v2i[1] = b ? co.z :  co.w;
            }
            float v4r[4], v4i[4];
            {
                const float4 co = *(const float4*)sCoef[1];
                const bool b = (c >> 2) & 1;
                const float g0r = b ? -co.y : co.x, g0i = b ? co.w : -co.z;
                const float g1r = b ?  co.x : co.y, g1i = b ? co.z :  co.w;
#pragma unroll
                for (int j = 0; j < 2; j++) {
                    v4r[2*j]   = v2r[j]*g0r - v2i[j]*g0i;
                    v4i[2*j]   = v2r[j]*g0i + v2i[j]*g0r;
                    v4r[2*j+1] = v2r[j]*g1r - v2i[j]*g1i;
                    v4i[2*j+1] = v2r[j]*g1i + v2i[j]*g1r;
                }
            }
            float v8r[8], v8i[8];
            {
                const float4 co = *(const float4*)sCoef[2];
                const bool b = (c >> 1) & 1;
                const float g0r = b ? -co.y : co.x, g0i = b ? co.w : -co.z;
                const float g1r = b ?  co.x : co.y, g1i = b ? co.z :  co.w;
#pragma unroll
                for (int j = 0; j < 4; j++) {
                    v8r[2*j]   = v4r[j]*g0r - v4i[j]*g0i;
                    v8i[2*j]   = v4r[j]*g0i + v4i[j]*g0r;
                    v8r[2*j+1] = v4r[j]*g1r - v4i[j]*g1i;
                    v8i[2*j+1] = v4r[j]*g1i + v4i[j]*g1r;
                }
            }
            {
                const float4 co = *(const float4*)sCoef[3];
                const bool b = c & 1;
                const float g0r = b ? -co.y : co.x, g0i = b ? co.w : -co.z;
                const float g1r = b ?  co.x : co.y, g1i = b ? co.z :  co.w;
#pragma unroll
                for (int j = 0; j < 8; j++) {
                    ur[2*j]   = v8r[j]*g0r - v8i[j]*g0i;
                    ui[2*j]   = v8r[j]*g0i + v8i[j]*g0r;
                    ur[2*j+1] = v8r[j]*g1r - v8i[j]*g1i;
                    ui[2*j+1] = v8r[j]*g1i + v8i[j]*g1r;
                }
            }
        }
        {
            float tr[DIM], ti[DIM];
#pragma unroll
            for (int r = 0; r < DIM; r++) { tr[r] = ur[finv(r)]; ti[r] = ui[finv(r)]; }
#pragma unroll
            for (int r = 0; r < DIM; r++) { ur[r] = tr[r]; ui[r] = ti[r]; }
        }

        // ---- layers 2,3: dense gates + ring ----
#pragma unroll
        for (int layer = 1; layer < 3; layer++) {
#pragma unroll
            for (int wi = 0; wi < NQ; wi++) {
                const int bit = 8 >> wi;
                const float4 co = *(const float4*)sCoef[layer * 4 + wi];
                const float p = co.x, q = co.y, u = co.z, w = co.w;
#pragma unroll
                for (int r = 0; r < DIM; r++) {
                    if (r & bit) continue;
                    const int r1 = r | bit;
                    const float v0r = ur[r], v0i = ui[r], v1r = ur[r1], v1i = ui[r1];
                    ur[r]  =  p * v0r + u * v0i - q * v1r - w * v1i;
                    ui[r]  = -u * v0r + p * v0i + w * v1r - q * v1i;
                    ur[r1] =  q * v0r - w * v0i + p * v1r - u * v1i;
                    ui[r1] =  w * v0r + q * v0i + u * v1r + p * v1i;
                }
            }
            {
                float tr[DIM], ti[DIM];
#pragma unroll
                for (int r = 0; r < DIM; r++) { tr[r] = ur[finv(r)]; ti[r] = ui[finv(r)]; }
#pragma unroll
                for (int r = 0; r < DIM; r++) { ur[r] = tr[r]; ui[r] = ti[r]; }
            }
        }

        if (lane < 16) {
#pragma unroll
            for (int r = 0; r < DIM; r++) { sUr[r][c] = ur[r]; sUi[r][c] = ui[r]; }
        }
        __syncwarp();

        {
            u32 frag[16];
#pragma unroll
            for (int nt = 0; nt < 2; nt++) {
                const int kk = 8 * nt + g;
                f16_split(sUr[kk][2 * t],     sUr[kk][2 * t + 1], frag[0 + 2 * nt], frag[8  + 2 * nt]);
                f16_split(sUr[kk][2 * t + 8], sUr[kk][2 * t + 9], frag[1 + 2 * nt], frag[9  + 2 * nt]);
                f16_split(sUi[kk][2 * t],     sUi[kk][2 * t + 1], frag[4 + 2 * nt], frag[12 + 2 * nt]);
                f16_split(sUi[kk][2 * t + 8], sUi[kk][2 * t + 9], frag[5 + 2 * nt], frag[13 + 2 * nt]);
            }
            uint4* dst = (uint4*)sBfrag[lane];
#pragma unroll
            for (int v = 0; v < 4; v++)
                dst[v] = make_uint4(frag[4 * v], frag[4 * v + 1], frag[4 * v + 2], frag[4 * v + 3]);
        }
        __syncwarp();   // scratch reads done before this warp overwrites its slice
    }

    // ---- Z-matrix B fragment (fp16 ±1) ----
    u32 Bz[2];
    {
        const u32 s0 = ((2 * t)     >> (3 - (g & 3))) & 1 ? 0xBC00u : 0x3C00u;
        const u32 s1 = ((2 * t + 1) >> (3 - (g & 3))) & 1 ? 0xBC00u : 0x3C00u;
        const u32 s2 = ((2 * t + 8) >> (3 - (g & 3))) & 1 ? 0xBC00u : 0x3C00u;
        const u32 s3 = ((2 * t + 9) >> (3 - (g & 3))) & 1 ? 0xBC00u : 0x3C00u;
        Bz[0] = s0 | (s1 << 16);
        Bz[1] = s2 | (s3 << 16);
        if (g >= 4) { Bz[0] = 0u; Bz[1] = 0u; }
    }

    u32 Bhr[2][2], Bhi[2][2], Blr[2][2], Bli[2][2];

#pragma unroll
    for (int batch = 0; batch < 2; batch++) {
        const int warpbase = blockIdx.x * 1024 + batch * 512 + wrp * 64;

        // ---- front phase: 2 patches/thread -> psi0 fp16 -> stage ----
        const float* basep[2];
#pragma unroll
        for (int pp = 0; pp < 2; pp++) {
            const int p  = warpbase + pp * 32 + lane;
            const int pc = (p < npatch) ? p : (npatch - 1);
            const int b  = pc / 196;
            const int q  = pc - b * 196;
            const int r  = q / 14;
            const int cc = q - r * 14;
            basep[pp] = x + b * 784 + r * 56 + cc * 2;
        }
        float2 V01[2], V23[2];
#pragma unroll
        for (int pp = 0; pp < 2; pp++) {
            V01[pp] = *(const float2*)(basep[pp]);
            V23[pp] = *(const float2*)(basep[pp] + 28);
        }

#pragma unroll
        for (int pp = 0; pp < 2; pp++) {
            float a0, b0, a1, b1, a2, b2, a3, b3;
            __sincosf(V01[pp].x * HPI, &b0, &a0);
            __sincosf(V01[pp].y * HPI, &b1, &a1);
            __sincosf(V23[pp].x * HPI, &b2, &a2);
            __sincosf(V23[pp].y * HPI, &b3, &a3);
            const float q01[4] = { a0 * a1, a0 * b1, b0 * a1, b0 * b1 };
            const float q23[4] = { a2 * a3, a2 * b3, b2 * a3, b2 * b3 };

            u32 ph[8];
#pragma unroll
            for (int m = 0; m < 8; m++) {
                const float f01 = q01[m >> 1];
                ph[m] = pack_f16x2(f01 * q23[(2 * m) & 3], f01 * q23[(2 * m + 1) & 3]);
            }

            uint4* slot = (uint4*)(ws + (pp * 32 + lane) * SLOT);
            slot[0] = make_uint4(ph[0], ph[1], ph[2], ph[3]);
            slot[1] = make_uint4(ph[4], ph[5], ph[6], ph[7]);
        }

        if (batch == 0) {
            __syncthreads();          // sBfrag + all staging visible
            const uint4* bfv = (const uint4*)sBfrag[lane];
            const uint4 vhr = bfv[0], vhi = bfv[1], vlr = bfv[2], vli = bfv[3];
            Bhr[0][0] = vhr.x; Bhr[0][1] = vhr.y; Bhr[1][0] = vhr.z; Bhr[1][1] = vhr.w;
            Bhi[0][0] = vhi.x; Bhi[0][1] = vhi.y; Bhi[1][0] = vhi.z; Bhi[1][1] = vhi.w;
            Blr[0][0] = vlr.x; Blr[0][1] = vlr.y; Blr[1][0] = vlr.z; Blr[1][1] = vlr.w;
            Bli[0][0] = vli.x; Bli[0][1] = vli.y; Bli[1][0] = vli.z; Bli[1][1] = vli.w;
        } else {
            __syncwarp();             // staging is warp-private
        }

        // ---- MMA phase: 4 tiles, 9 MMAs each ----
#pragma unroll
        for (int T = 0; T < 4; T++) {
            u32 Aph[4];
            ldsm_x4(Aph, rowa + T * 16 * SLOT);

            float Cr[2][4], Ci[2][4];
#pragma unroll
            for (int nt = 0; nt < 2; nt++)
#pragma unroll
                for (int k = 0; k < 4; k++) { Cr[nt][k] = 0.0f; Ci[nt][k] = 0.0f; }

#pragma unroll
            for (int nt = 0; nt < 2; nt++) {
                mma_f16(Cr[nt], Aph, Bhr[nt]);   // Uh * Ph
                mma_f16(Cr[nt], Aph, Blr[nt]);   // Ul * Ph
                mma_f16(Ci[nt], Aph, Bhi[nt]);
                mma_f16(Ci[nt], Aph, Bli[nt]);
            }

            float pr[2][4];
#pragma unroll
            for (int nt = 0; nt < 2; nt++)
#pragma unroll
                for (int k = 0; k < 4; k++)
                    pr[nt][k] = fmaf(Cr[nt][k], Cr[nt][k], Ci[nt][k] * Ci[nt][k]);

            u32 Ap[4];
            Ap[0] = pack_f16x2(pr[0][0], pr[0][1]);
            Ap[1] = pack_f16x2(pr[0][2], pr[0][3]);
            Ap[2] = pack_f16x2(pr[1][0], pr[1][1]);
            Ap[3] = pack_f16x2(pr[1][2], pr[1][3]);

            float E[4] = {0.0f, 0.0f, 0.0f, 0.0f};
            mma_f16(E, Ap, Bz);

            if (t < 2) {
                const int p0s = warpbase + T * 16 + g;
                const int p1s = p0s + 8;
                if (p0s < npatch) *(float2*)(out + 4 * p0s + 2 * t) = make_float2(E[0], E[1]);
                if (p1s < npatch) *(float2*)(out + 4 * p1s + 2 * t) = make_float2(E[2], E[3]);
            }
        }

        if (batch == 0) __syncwarp();  // MMA reads done before batch-1 restage
    }
}

extern "C" void kernel_launch(void* const* d_in, const int* in_sizes, int n_in,
                              void* d_out, int out_size) {
    const float* x      = (const float*)d_in[0];
    const float* params = (const float*)d_in[1];
    float* out = (float*)d_out;

    const int bsz    = in_sizes[0] / 784;
    const int npatch = bsz * 196;

    const int blocks = (npatch + 1023) / 1024;
    quanv_kernel<<<blocks, 256>>>(x, params, out, npatch);
}